// round 9
// baseline (speedup 1.0000x reference)
#include <cuda_runtime.h>
#include <cuda_fp16.h>
#include <cstdint>
#include <cstddef>

#define DM 768
#define DI 1536
#define DS 16
#define DR 48
#define BB 2
#define LL 1024
#define TT (BB*LL)
#define NPROJ 80
#define NXZ 3072          // xs(1536) + z(1536) fused in-proj
#define K2_IN  1536       // 2*768
#define K2_BIG 3072       // 2*1536
#define K2_DT  128        // 2*64 (48 padded to 64)
#define SK_PJ 6
#define SK_OUT 3

// ======================= scratch (device globals) =======================
__device__ __align__(128) float g_xz[TT*NXZ];
__device__ __align__(128) __half g_x2[(size_t)TT*K2_IN];
__device__ __align__(128) __half g_Wcat2[(size_t)NXZ*K2_IN];
__device__ __align__(128) float g_xc[2][TT*DI];
__device__ __align__(128) __half g_xc2[2][(size_t)TT*K2_BIG];
__device__ __align__(128) float g_wproj[2][NPROJ*DI];
__device__ __align__(128) __half g_wproj2[2][(size_t)NPROJ*K2_BIG];
__device__ __align__(128) float g_pj[2][TT*NPROJ];
__device__ __align__(128) __half g_pj2[2][(size_t)TT*K2_DT];
__device__ __align__(128) __half g_dtW2[2][(size_t)DI*K2_DT];
__device__ __align__(128) float g_delta[2][TT*DI];
__device__ __align__(128) float g_y[2][TT*DI];
__device__ __align__(128) __half g_yc2[(size_t)TT*K2_BIG];
__device__ __align__(128) __half g_Wout2[(size_t)DM*K2_BIG];
__device__ __align__(128) float g_part[(size_t)SK_OUT*TT*DM];

__device__ __forceinline__ float siluf(float x) { return x / (1.0f + __expf(-x)); }
__device__ __forceinline__ float softplusf(float x) {
    return (x > 20.0f) ? x : log1pf(__expf(x));
}
__device__ __forceinline__ void split2(float v, __half& hi, __half& lo) {
    hi = __float2half_rn(v);
    lo = __float2half_rn(v - __half2float(hi));
}
// pack 4 halves -> uint2 (8B store)
__device__ __forceinline__ uint2 pack4(__half a, __half b, __half c, __half d) {
    __half2 p0 = __halves2half2(a, b);
    __half2 p1 = __halves2half2(c, d);
    uint2 u;
    u.x = *reinterpret_cast<uint32_t*>(&p0);
    u.y = *reinterpret_cast<uint32_t*>(&p1);
    return u;
}
// split float4 -> hi uint2 + lo uint2
__device__ __forceinline__ void split4(float4 v, uint2& hi, uint2& lo) {
    __half h0, l0, h1, l1, h2, l2, h3, l3;
    split2(v.x, h0, l0); split2(v.y, h1, l1);
    split2(v.z, h2, l2); split2(v.w, h3, l3);
    hi = pack4(h0, h1, h2, h3);
    lo = pack4(l0, l1, l2, l3);
}

// =============== fp16-double conversion (vec4) ============================
// isA: segs {hi, lo};  !isA: segs {hi, hi}
__global__ void conv2_kernel(const float* __restrict__ src, int lds, int Kreal,
                             int Kseg, __half* __restrict__ dst, int isA,
                             int total4)
{
    int idx = blockIdx.x * blockDim.x + threadIdx.x;
    if (idx >= total4) return;
    int kseg4 = Kseg >> 2;
    int r = idx / kseg4, k = (idx - r * kseg4) << 2;
    float4 v = (k < Kreal) ? *(const float4*)(src + (size_t)r * lds + k)
                           : make_float4(0.f, 0.f, 0.f, 0.f);
    uint2 hi, lo; split4(v, hi, lo);
    size_t base = (size_t)r * 2 * Kseg;
    *(uint2*)(dst + base + k) = hi;
    *(uint2*)(dst + base + Kseg + k) = isA ? lo : hi;
}

// =============== concat dt/B/C weights (vec4) ==============================
__global__ void concat_wproj(const float* __restrict__ Wdt, const float* __restrict__ WB,
                             const float* __restrict__ WC,
                             const float* __restrict__ Wdtb, const float* __restrict__ WBb,
                             const float* __restrict__ WCb,
                             float* __restrict__ w0, float* __restrict__ w1)
{
    int idx = blockIdx.x * blockDim.x + threadIdx.x;
    if (idx >= NPROJ * DI / 4) return;
    int r = idx / (DI / 4), c = (idx - r * (DI / 4)) << 2;
    float4 vf, vb;
    if (r < 48)      { vf = *(const float4*)(Wdt + (size_t)r * DI + c);
                       vb = *(const float4*)(Wdtb + (size_t)r * DI + c); }
    else if (r < 64) { vf = *(const float4*)(WB + (size_t)(r - 48) * DI + c);
                       vb = *(const float4*)(WBb + (size_t)(r - 48) * DI + c); }
    else             { vf = *(const float4*)(WC + (size_t)(r - 64) * DI + c);
                       vb = *(const float4*)(WCb + (size_t)(r - 64) * DI + c); }
    *(float4*)(w0 + (size_t)r * DI + c) = vf;
    *(float4*)(w1 + (size_t)r * DI + c) = vb;
}

// =============== fused remaining weight conversions (vec4, B-side) ========
#define RW0_4 (NPROJ*DI/4)
#define RW1_4 (2*NPROJ*DI/4)
#define RW2_4 (RW1_4 + DI*64/4)
#define RW3_4 (RW1_4 + 2*DI*64/4)
#define RWT_4 (RW3_4 + DM*DI/4)
__global__ void prep_rest_kernel(const float* __restrict__ wp0, const float* __restrict__ wp1,
                                 const float* __restrict__ dtW, const float* __restrict__ dtWb,
                                 const float* __restrict__ Wout,
                                 __half* __restrict__ wp2f, __half* __restrict__ wp2b,
                                 __half* __restrict__ dtW2f, __half* __restrict__ dtW2b,
                                 __half* __restrict__ Wout2)
{
    int idx = blockIdx.x * blockDim.x + threadIdx.x;
    if (idx >= RWT_4) return;
    const float* src; __half* dst; int lds, Kreal, Kseg, local;
    if (idx < RW0_4)      { local = idx;          src = wp0;  dst = wp2f;  lds = DI; Kreal = DI; Kseg = DI; }
    else if (idx < RW1_4) { local = idx - RW0_4;  src = wp1;  dst = wp2b;  lds = DI; Kreal = DI; Kseg = DI; }
    else if (idx < RW2_4) { local = idx - RW1_4;  src = dtW;  dst = dtW2f; lds = DR; Kreal = DR; Kseg = 64; }
    else if (idx < RW3_4) { local = idx - RW2_4;  src = dtWb; dst = dtW2b; lds = DR; Kreal = DR; Kseg = 64; }
    else                  { local = idx - RW3_4;  src = Wout; dst = Wout2; lds = DI; Kreal = DI; Kseg = DI; }
    int kseg4 = Kseg >> 2;
    int r = local / kseg4, k = (local - r * kseg4) << 2;
    float4 v = (k < Kreal) ? *(const float4*)(src + (size_t)r * lds + k)
                           : make_float4(0.f, 0.f, 0.f, 0.f);
    uint2 hi, lo; split4(v, hi, lo);
    size_t base = (size_t)r * 2 * Kseg;
    *(uint2*)(dst + base + k) = hi;
    *(uint2*)(dst + base + Kseg + k) = hi;
}

// ======================= mma.sync fp16 NT GEMM (cp.async 4-stage) =========
#define BM 64
#define GBK 32
#define GLDS 40
#define NSTAGE 4
#define A_HALF (BM*80)
#define STAGE_B (A_HALF + 128*80)
#define GSMEM (NSTAGE*STAGE_B)
#define MT 2

__device__ __forceinline__ void ldsm4(uint32_t* r, uint32_t addr) {
    asm volatile("ldmatrix.sync.aligned.m8n8.x4.shared.b16 {%0,%1,%2,%3}, [%4];"
                 : "=r"(r[0]), "=r"(r[1]), "=r"(r[2]), "=r"(r[3]) : "r"(addr));
}
__device__ __forceinline__ void mma16816(float* d, const uint32_t* a,
                                         uint32_t b0, uint32_t b1) {
    asm volatile("mma.sync.aligned.m16n8k16.row.col.f32.f16.f16.f32 "
                 "{%0,%1,%2,%3}, {%4,%5,%6,%7}, {%8,%9}, {%0,%1,%2,%3};"
                 : "+f"(d[0]), "+f"(d[1]), "+f"(d[2]), "+f"(d[3])
                 : "r"(a[0]), "r"(a[1]), "r"(a[2]), "r"(a[3]), "r"(b0), "r"(b1));
}
__device__ __forceinline__ void cpa16(uint32_t dst, const void* src, int sz) {
    asm volatile("cp.async.cg.shared.global [%0], [%1], 16, %2;"
                 :: "r"(dst), "l"(src), "r"(sz) : "memory");
}
__device__ __forceinline__ void cpa_commit() {
    asm volatile("cp.async.commit_group;" ::: "memory");
}
__device__ __forceinline__ void cpa_wait2() {
    asm volatile("cp.async.wait_group 2;" ::: "memory");
}

__global__ __launch_bounds__(256, 3)
void gemm_mma(const __half* __restrict__ A0, const __half* __restrict__ A1,
              const __half* __restrict__ B0, const __half* __restrict__ B1,
              float* __restrict__ C0, float* __restrict__ C1,
              int ldc, int K2, int Nreal,
              const float* __restrict__ bias0, const float* __restrict__ bias1, int act,
              __half* __restrict__ D20, __half* __restrict__ D21,
              int splitk, float* __restrict__ P)
{
    extern __shared__ char smem[];

    const int zall = blockIdx.z;
    const int z = zall / splitk;
    const int sk = zall - z * splitk;
    const int K2eff = K2 / splitk;
    const int kbase = sk * K2eff;

    const __half* A = z ? A1 : A0;
    const __half* B = z ? B1 : B0;

    const int tid = threadIdx.x;
    const int lane = tid & 31;
    const int wid = tid >> 5;
    const int bm0 = blockIdx.y * BM;
    const int bn0 = blockIdx.x * 128;
    const int wm = (wid >> 2) * 32;
    const int wn = (wid & 3) * 32;

    const uint32_t sBase = (uint32_t)__cvta_generic_to_shared(smem);
    const int lr = lane & 15, lh = lane >> 4;

    float acc[MT][4][4];
#pragma unroll
    for (int i = 0; i < MT; i++)
#pragma unroll
        for (int j = 0; j < 4; j++)
#pragma unroll
            for (int v = 0; v < 4; v++) acc[i][j][v] = 0.0f;

    const int nt = K2eff / GBK;

    const int arow = tid >> 2, ach = tid & 3;
    const __half* Ap = A + (size_t)(bm0 + arow) * K2 + kbase + ach * 8;
    const int brow0 = bn0 + arow;
    const int brow1 = bn0 + arow + 64;
    const int bsz0 = (brow0 < Nreal) ? 16 : 0;
    const int bsz1 = (brow1 < Nreal) ? 16 : 0;
    const __half* Bp0 = B + (size_t)((brow0 < Nreal) ? brow0 : 0) * K2 + kbase + ach * 8;
    const __half* Bp1 = B + (size_t)((brow1 < Nreal) ? brow1 : 0) * K2 + kbase + ach * 8;
    const uint32_t sA = (uint32_t)(arow * 80 + ach * 16);
    const uint32_t sB0 = A_HALF + sA;
    const uint32_t sB1 = A_HALF + sA + 64 * 80;

    auto load_stage = [&](int s, int t) {
        uint32_t sb = sBase + (uint32_t)s * STAGE_B;
        size_t koff = (size_t)t * GBK;
        cpa16(sb + sA, Ap + koff, 16);
        cpa16(sb + sB0, Bp0 + koff, bsz0);
        cpa16(sb + sB1, Bp1 + koff, bsz1);
    };

#pragma unroll
    for (int s = 0; s < NSTAGE - 1; s++) {
        if (s < nt) load_stage(s, s);
        cpa_commit();
    }

    for (int t = 0; t < nt; t++) {
        cpa_wait2();
        __syncthreads();

        int tn = t + NSTAGE - 1;
        if (tn < nt) load_stage(tn & (NSTAGE - 1), tn);
        cpa_commit();

        uint32_t aoff = sBase + (uint32_t)(t & (NSTAGE - 1)) * STAGE_B;
        uint32_t boff = aoff + A_HALF;
#pragma unroll
        for (int ks = 0; ks < 2; ks++) {
            uint32_t af[MT][4];
#pragma unroll
            for (int mt = 0; mt < MT; mt++)
                ldsm4(af[mt], aoff + ((wm + mt * 16 + lr) * GLDS + ks * 16 + lh * 8) * 2);
            uint32_t bf[2][4];
#pragma unroll
            for (int bt = 0; bt < 2; bt++)
                ldsm4(bf[bt], boff + ((wn + bt * 16 + lr) * GLDS + ks * 16 + lh * 8) * 2);
#pragma unroll
            for (int mt = 0; mt < MT; mt++) {
#pragma unroll
                for (int ntile = 0; ntile < 4; ntile++) {
                    int bt = ntile >> 1, sub = ntile & 1;
                    mma16816(acc[mt][ntile], af[mt], bf[bt][sub], bf[bt][sub + 2]);
                }
            }
        }
    }

    const int em = lane >> 2;
    const int en = (lane & 3) * 2;

    if (splitk > 1) {
        float* Cp = P + (size_t)zall * TT * ldc;
#pragma unroll
        for (int mt = 0; mt < MT; mt++) {
#pragma unroll
            for (int ntile = 0; ntile < 4; ntile++) {
                int n = bn0 + wn + ntile * 8 + en;
                if (n >= Nreal) continue;
                int m = bm0 + wm + mt * 16 + em;
                *(float2*)(Cp + (size_t)m * ldc + n) =
                    make_float2(acc[mt][ntile][0], acc[mt][ntile][1]);
                *(float2*)(Cp + (size_t)(m + 8) * ldc + n) =
                    make_float2(acc[mt][ntile][2], acc[mt][ntile][3]);
            }
        }
        return;
    }

    float* C = z ? C1 : C0;
    const float* bias = z ? bias1 : bias0;
    __half* D2 = z ? D21 : D20;
#pragma unroll
    for (int mt = 0; mt < MT; mt++) {
#pragma unroll
        for (int ntile = 0; ntile < 4; ntile++) {
            int n = bn0 + wn + ntile * 8 + en;
            if (n >= Nreal) continue;
            int m = bm0 + wm + mt * 16 + em;
            float2 v0 = make_float2(acc[mt][ntile][0], acc[mt][ntile][1]);
            float2 v1 = make_float2(acc[mt][ntile][2], acc[mt][ntile][3]);
            if (bias) {
                float b0v = bias[n], b1v = bias[n + 1];
                v0.x += b0v; v0.y += b1v; v1.x += b0v; v1.y += b1v;
            }
            if (act == 1) {
                v0.x = softplusf(v0.x); v0.y = softplusf(v0.y);
                v1.x = softplusf(v1.x); v1.y = softplusf(v1.y);
            }
            *(float2*)(C + (size_t)m * ldc + n) = v0;
            *(float2*)(C + (size_t)(m + 8) * ldc + n) = v1;
            if (D2 && n < 48) {
                __half hi, lo;
                __half* p0 = D2 + (size_t)m * K2_DT;
                split2(v0.x, hi, lo); p0[n] = hi; p0[64 + n] = lo;
                split2(v0.y, hi, lo); p0[n+1] = hi; p0[64 + n+1] = lo;
                __half* p1 = D2 + (size_t)(m + 8) * K2_DT;
                split2(v1.x, hi, lo); p1[n] = hi; p1[64 + n] = lo;
                split2(v1.y, hi, lo); p1[n+1] = hi; p1[64 + n+1] = lo;
            }
        }
    }
}

// ====== proj split-K reduce (vec4, deterministic) + pj2 fusion ============
__global__ void reduce_proj_kernel(const float* __restrict__ P,
                                   float* __restrict__ pj0, float* __restrict__ pj1,
                                   __half* __restrict__ pj2f, __half* __restrict__ pj2b)
{
    int idx = blockIdx.x * blockDim.x + threadIdx.x;
    if (idx >= 2 * TT * NPROJ / 4) return;
    int per_dir = TT * NPROJ / 4;
    int dir = idx / per_dir;
    int rem = idx - dir * per_dir;
    int m = rem / (NPROJ / 4), n = (rem - m * (NPROJ / 4)) << 2;
    const float* base = P + (size_t)dir * SK_PJ * TT * NPROJ + (size_t)m * NPROJ + n;
    float4 s = make_float4(0.f, 0.f, 0.f, 0.f);
#pragma unroll
    for (int sk = 0; sk < SK_PJ; sk++) {
        float4 v = *(const float4*)(base + (size_t)sk * TT * NPROJ);
        s.x += v.x; s.y += v.y; s.z += v.z; s.w += v.w;
    }
    *(float4*)((dir ? pj1 : pj0) + (size_t)m * NPROJ + n) = s;
    if (n < 48) {
        uint2 hi, lo; split4(s, hi, lo);
        __half* p2 = (dir ? pj2b : pj2f) + (size_t)m * K2_DT;
        *(uint2*)(p2 + n) = hi;
        *(uint2*)(p2 + 64 + n) = lo;
    }
}

// ====== out split-K reduce (vec4, deterministic) ===========================
__global__ void reduce_out_kernel(const float* __restrict__ P, float* __restrict__ out)
{
    int idx = blockIdx.x * blockDim.x + threadIdx.x;
    if (idx >= TT * DM / 4) return;
    size_t o = (size_t)idx << 2;
    float4 a = *(const float4*)(P + o);
    float4 b = *(const float4*)(P + (size_t)TT * DM + o);
    float4 c = *(const float4*)(P + (size_t)2 * TT * DM + o);
    *(float4*)(out + o) = make_float4(a.x + b.x + c.x, a.y + b.y + c.y,
                                      a.z + b.z + c.z, a.w + b.w + c.w);
}

// =============== causal depthwise conv + silu + fp16 double (vec4) ========
__global__ void conv_silu_kernel(const float* __restrict__ xz,
                                 const float* __restrict__ cw, const float* __restrict__ cb,
                                 const float* __restrict__ cwb, const float* __restrict__ cbb,
                                 float* __restrict__ xcf, float* __restrict__ xcbk,
                                 __half* __restrict__ xc2f,
                                 __half* __restrict__ xc2b)
{
    int idx = blockIdx.x * blockDim.x + threadIdx.x;
    if (idx >= TT * DI / 4) return;
    int dv = idx % (DI / 4);
    int d = dv << 2;
    int t = (idx / (DI / 4)) % LL;
    int b = idx / ((DI / 4) * LL);
    const float* xb = xz + (size_t)b * LL * NXZ + d;

    float wF[4][4], wB4[4][4];
#pragma unroll
    for (int i = 0; i < 4; i++) {
        *(float4*)&wF[i][0]  = *(const float4*)(cw  + (size_t)(d + i) * 4);
        *(float4*)&wB4[i][0] = *(const float4*)(cwb + (size_t)(d + i) * 4);
    }
    float accF[4], accB[4];
    float4 cbF = *(const float4*)(cb + d);
    float4 cbB = *(const float4*)(cbb + d);
    accF[0] = cbF.x; accF[1] = cbF.y; accF[2] = cbF.z; accF[3] = cbF.w;
    accB[0] = cbB.x; accB[1] = cbB.y; accB[2] = cbB.z; accB[3] = cbB.w;

    int base = (LL - 1) - t;
#pragma unroll
    for (int j = 0; j < 4; j++) {
        if (t >= 3 - j) {
            float4 xf = *(const float4*)(xb + (size_t)(t - (3 - j)) * NXZ);
            accF[0] = fmaf(xf.x, wF[0][j], accF[0]);
            accF[1] = fmaf(xf.y, wF[1][j], accF[1]);
            accF[2] = fmaf(xf.z, wF[2][j], accF[2]);
            accF[3] = fmaf(xf.w, wF[3][j], accF[3]);
            float4 xr = *(const float4*)(xb + (size_t)(base + (3 - j)) * NXZ);
            accB[0] = fmaf(xr.x, wB4[0][j], accB[0]);
            accB[1] = fmaf(xr.y, wB4[1][j], accB[1]);
            accB[2] = fmaf(xr.z, wB4[2][j], accB[2]);
            accB[3] = fmaf(xr.w, wB4[3][j], accB[3]);
        }
    }
    float4 vF = make_float4(siluf(accF[0]), siluf(accF[1]), siluf(accF[2]), siluf(accF[3]));
    float4 vB = make_float4(siluf(accB[0]), siluf(accB[1]), siluf(accB[2]), siluf(accB[3]));

    size_t r = (size_t)(b * LL + t);
    *(float4*)(xcf + r * DI + d) = vF;
    *(float4*)(xcbk + r * DI + d) = vB;
    uint2 hi, lo;
    split4(vF, hi, lo);
    __half* d2 = xc2f + r * K2_BIG;
    *(uint2*)(d2 + d) = hi; *(uint2*)(d2 + DI + d) = lo;
    split4(vB, hi, lo);
    d2 = xc2b + r * K2_BIG;
    *(uint2*)(d2 + d) = hi; *(uint2*)(d2 + DI + d) = lo;
}

// ======================= selective scan (unchanged) =======================
__global__ __launch_bounds__(256)
void scan_kernel(const float* __restrict__ xc0, const float* __restrict__ xc1,
                 const float* __restrict__ dl0, const float* __restrict__ dl1,
                 const float* __restrict__ pj0, const float* __restrict__ pj1,
                 const float* __restrict__ Alog0, const float* __restrict__ Alog1,
                 const float* __restrict__ Dp0, const float* __restrict__ Dp1,
                 float* __restrict__ y0, float* __restrict__ y1)
{
    int bid = blockIdx.x;
    int dgroup = bid % 96;
    int b = (bid / 96) % BB;
    int dir = bid / (96 * BB);

    const float* xc = dir ? xc1 : xc0;
    const float* dl = dir ? dl1 : dl0;
    const float* pj = dir ? pj1 : pj0;
    const float* Alog = dir ? Alog1 : Alog0;
    const float* Dp = dir ? Dp1 : Dp0;
    float* y = dir ? y1 : y0;

    int lane = threadIdx.x & 31;
    int w = threadIdx.x >> 5;
    int n = lane & 15;
    int d = dgroup * 16 + w * 2 + (lane >> 4);

    const float* xcp = xc + (size_t)b * LL * DI + d;
    const float* dlp = dl + (size_t)b * LL * DI + d;
    const float* pjB = pj + (size_t)b * LL * NPROJ + 48 + n;
    const float* pjC = pj + (size_t)b * LL * NPROJ + 64 + n;
    float* yp = y + (size_t)b * LL * DI + d;

    const float A = -__expf(Alog[d * DS + n]);
    const float Dd = Dp[d];

    float h = 0.0f;
    float dv = dlp[0], xv = xcp[0], Bv = pjB[0], Cv = pjC[0];

    for (int t = 0; t < LL; ++t) {
        float dv2 = 0.f, xv2 = 0.f, Bv2 = 0.f, Cv2 = 0.f;
        if (t + 1 < LL) {
            dv2 = dlp[(size_t)(t + 1) * DI];
            xv2 = xcp[(size_t)(t + 1) * DI];
            Bv2 = pjB[(size_t)(t + 1) * NPROJ];
            Cv2 = pjC[(size_t)(t + 1) * NPROJ];
        }
        float dA = __expf(dv * A);
        h = fmaf(dA, h, dv * xv * Bv);
        float p = h * Cv;
        p += __shfl_xor_sync(0xffffffffu, p, 1);
        p += __shfl_xor_sync(0xffffffffu, p, 2);
        p += __shfl_xor_sync(0xffffffffu, p, 4);
        p += __shfl_xor_sync(0xffffffffu, p, 8);
        if (n == 0) yp[(size_t)t * DI] = fmaf(Dd, xv, p);
        dv = dv2; xv = xv2; Bv = Bv2; Cv = Cv2;
    }
}

// ========== combine (vec4): 0.5*silu(z)*(y_f + rev(y_b)) -> fp16 double ====
__global__ void combine_kernel(const float* __restrict__ xz,
                               const float* __restrict__ yf,
                               const float* __restrict__ yb,
                               __half* __restrict__ yc2)
{
    int idx = blockIdx.x * blockDim.x + threadIdx.x;
    if (idx >= TT * DI / 4) return;
    int d = (idx % (DI / 4)) << 2;
    int l = (idx / (DI / 4)) % LL;
    int b = idx / ((DI / 4) * LL);
    float4 zz = *(const float4*)(xz + ((size_t)b * LL + l) * NXZ + DI + d);
    float4 yv = *(const float4*)(yf + ((size_t)idx << 2));
    float4 rv = *(const float4*)(yb + ((size_t)b * LL + (LL - 1 - l)) * DI + d);
    float4 v;
    v.x = 0.5f * siluf(zz.x) * (yv.x + rv.x);
    v.y = 0.5f * siluf(zz.y) * (yv.y + rv.y);
    v.z = 0.5f * siluf(zz.z) * (yv.z + rv.z);
    v.w = 0.5f * siluf(zz.w) * (yv.w + rv.w);
    uint2 hi, lo; split4(v, hi, lo);
    __half* d2 = yc2 + ((size_t)b * LL + l) * K2_BIG;
    *(uint2*)(d2 + d) = hi;
    *(uint2*)(d2 + DI + d) = lo;
}

// ======================= launch ==========================================
extern "C" void kernel_launch(void* const* d_in, const int* in_sizes, int n_in,
                              void* d_out, int out_size)
{
    const float* x        = (const float*)d_in[0];
    const float* W_in_s   = (const float*)d_in[1];
    const float* W_in_g   = (const float*)d_in[2];
    const float* conv_w   = (const float*)d_in[3];
    const float* conv_b   = (const float*)d_in[4];
    const float* conv_w_b = (const float*)d_in[5];
    const float* conv_b_b = (const float*)d_in[6];
    const float* W_dt     = (const float*)d_in[7];
    const float* W_B      = (const float*)d_in[8];
    const float* W_C      = (const float*)d_in[9];
    const float* dtW      = (const float*)d_in[10];
    const float* dtb      = (const float*)d_in[11];
    const float* A_log    = (const float*)d_in[12];
    const float* Dp       = (const float*)d_in[13];
    const float* W_dt_b   = (const float*)d_in[14];
    const float* W_B_b    = (const float*)d_in[15];
    const float* W_C_b    = (const float*)d_in[16];
    const float* dtW_b    = (const float*)d_in[17];
    const float* dtb_b    = (const float*)d_in[18];
    const float* A_log_b  = (const float*)d_in[19];
    const float* Dp_b     = (const float*)d_in[20];
    const float* W_out    = (const float*)d_in[21];
    float* out = (float*)d_out;

    cudaFuncSetAttribute(gemm_mma, cudaFuncAttributeMaxDynamicSharedMemorySize, GSMEM);

    float *p_xz, *p_xc, *p_wp, *p_pj, *p_dl, *p_y, *p_part;
    __half *p_x2, *p_Wcat2, *p_xc2, *p_wp2, *p_pj2, *p_dtW2, *p_yc2, *p_Wout2;
    cudaGetSymbolAddress((void**)&p_xz, g_xz);
    cudaGetSymbolAddress((void**)&p_x2, g_x2);
    cudaGetSymbolAddress((void**)&p_Wcat2, g_Wcat2);
    cudaGetSymbolAddress((void**)&p_xc, g_xc);
    cudaGetSymbolAddress((void**)&p_xc2, g_xc2);
    cudaGetSymbolAddress((void**)&p_wp, g_wproj);
    cudaGetSymbolAddress((void**)&p_wp2, g_wproj2);
    cudaGetSymbolAddress((void**)&p_pj, g_pj);
    cudaGetSymbolAddress((void**)&p_pj2, g_pj2);
    cudaGetSymbolAddress((void**)&p_dtW2, g_dtW2);
    cudaGetSymbolAddress((void**)&p_dl, g_delta);
    cudaGetSymbolAddress((void**)&p_y, g_y);
    cudaGetSymbolAddress((void**)&p_yc2, g_yc2);
    cudaGetSymbolAddress((void**)&p_Wout2, g_Wout2);
    cudaGetSymbolAddress((void**)&p_part, g_part);

    float* xc0 = p_xc;  float* xc1 = p_xc + (size_t)TT * DI;
    float* pj0 = p_pj;  float* pj1 = p_pj + (size_t)TT * NPROJ;
    float* dl0 = p_dl;  float* dl1 = p_dl + (size_t)TT * DI;
    float* y0  = p_y;   float* y1  = p_y + (size_t)TT * DI;
    float* wp0 = p_wp;  float* wp1 = p_wp + (size_t)NPROJ * DI;
    __half* xc2f = p_xc2;
    __half* xc2b = p_xc2 + (size_t)TT * K2_BIG;
    __half* wp2f = p_wp2;
    __half* wp2b = p_wp2 + (size_t)NPROJ * K2_BIG;
    __half* pj2f = p_pj2;
    __half* pj2b = p_pj2 + (size_t)TT * K2_DT;
    __half* dtW2f = p_dtW2;
    __half* dtW2b = p_dtW2 + (size_t)DI * K2_DT;

    auto cgrid = [](int total) { return (total + 255) / 256; };
    const int nV4 = TT * DI / 4;

    // --- in-proj prerequisites (GEMM stays at our launch idx 3) ---
    conv2_kernel<<<cgrid(TT * DM / 4), 256>>>(x, DM, DM, DM, p_x2, 1, TT * DM / 4);
    conv2_kernel<<<cgrid(DI * DM / 4), 256>>>(W_in_s, DM, DM, DM, p_Wcat2, 0, DI * DM / 4);
    conv2_kernel<<<cgrid(DI * DM / 4), 256>>>(W_in_g, DM, DM, DM,
                                              p_Wcat2 + (size_t)DI * K2_IN, 0, DI * DM / 4);

    // in-proj: xz[T,3072] = x2 @ Wcat2^T
    gemm_mma<<<dim3(NXZ / 128, TT / BM, 1), 256, GSMEM>>>(
        p_x2, p_x2, p_Wcat2, p_Wcat2, p_xz, p_xz, NXZ, K2_IN, NXZ,
        nullptr, nullptr, 0, nullptr, nullptr, 1, nullptr);

    // remaining weight prep
    concat_wproj<<<cgrid(NPROJ * DI / 4), 256>>>(W_dt, W_B, W_C, W_dt_b, W_B_b, W_C_b, wp0, wp1);
    prep_rest_kernel<<<cgrid(RWT_4), 256>>>(wp0, wp1, dtW, dtW_b, W_out,
                                            wp2f, wp2b, dtW2f, dtW2b, p_Wout2);

    // conv + silu + fp16 double
    conv_silu_kernel<<<cgrid(nV4), 256>>>(p_xz, conv_w, conv_b, conv_w_b, conv_b_b,
                                          xc0, xc1, xc2f, xc2b);

    // proj: split-K=6 partials (both dirs) -> reduce (+ fused pj2)
    gemm_mma<<<dim3(1, TT / BM, 2 * SK_PJ), 256, GSMEM>>>(
        xc2f, xc2b, wp2f, wp2b, nullptr, nullptr, NPROJ, K2_BIG, NPROJ,
        nullptr, nullptr, 0, nullptr, nullptr, SK_PJ, p_part);
    reduce_proj_kernel<<<cgrid(2 * TT * NPROJ / 4), 256>>>(p_part, pj0, pj1, pj2f, pj2b);

    // delta = softplus(pj2 @ dtW2^T + dtb) (both dirs)
    gemm_mma<<<dim3(DI / 128, TT / BM, 2), 256, GSMEM>>>(
        pj2f, pj2b, dtW2f, dtW2b, dl0, dl1, DI, K2_DT, DI,
        dtb, dtb_b, 1, nullptr, nullptr, 1, nullptr);

    // selective scan
    scan_kernel<<<2 * BB * (DI / 16), 256>>>(
        xc0, xc1, dl0, dl1, pj0, pj1, A_log, A_log_b, Dp, Dp_b, y0, y1);

    // combine -> yc2 (fp16 double)
    combine_kernel<<<cgrid(nV4), 256>>>(p_xz, y0, y1, p_yc2);

    // out-proj: split-K=3 partials -> reduce
    gemm_mma<<<dim3(DM / 128, TT / BM, SK_OUT), 256, GSMEM>>>(
        p_yc2, p_yc2, p_Wout2, p_Wout2, nullptr, nullptr, DM, K2_BIG, DM,
        nullptr, nullptr, 0, nullptr, nullptr, SK_OUT, p_part);
    reduce_out_kernel<<<cgrid(TT * DM / 4), 256>>>(p_part, out);
}